// round 15
// baseline (speedup 1.0000x reference)
#include <cuda_runtime.h>
#include <math.h>
#include <stdint.h>

#define S_LEN 512
#define BATCH 64
#define IN_SZ 256
#define HID   1024
#define NCTA  128
#define CPC   8            // columns per CTA = HID/NCTA
#define TPB2  512          // recurrence threads: 16 warps
#define BH    (BATCH * HID)

typedef unsigned long long ull;

// packed f32x2 FMA exists only in the arch-specific ('a') compilation pass
#if (defined(__CUDA_ARCH_FEAT_SM103_ALL) || \
     (defined(__CUDA_ARCH_SPECIFIC__) && (__CUDA_ARCH_SPECIFIC__ == 1030)))
#define HAS_F32X2 1
#else
#define HAS_F32X2 0
#endif

// ---------------- scratch / sync state (no allocs allowed) ----------------
__device__ float    g_xv[(size_t)S_LEN * BATCH * HID];   // x@V + b + b2
__device__ unsigned g_count = 0;     // startup barrier arrivals (monotone)
__device__ unsigned g_phase = 0;     // startup barrier generation (monotone)
__device__ unsigned g_gc[8 * 32];    // 8 group counters, one per 128B line

// ---------------- startup-only full grid barrier (proven R4 scheme) ---------
__device__ __forceinline__ void grid_arrive() {
    unsigned ticket;
    asm volatile("atom.add.acq_rel.gpu.u32 %0, [%1], 1;"
                 : "=r"(ticket) : "l"(&g_count) : "memory");
    if ((ticket & (NCTA - 1)) == (NCTA - 1)) {
        asm volatile("red.add.release.gpu.u32 [%0], 1;"
                     :: "l"(&g_phase) : "memory");
    }
}
__device__ __forceinline__ void grid_wait(unsigned target) {
    unsigned p;
    do {
        asm volatile("ld.acquire.gpu.u32 %0, [%1];"
                     : "=r"(p) : "l"(&g_phase) : "memory");
    } while ((int)(p - target) < 0);
}

// ---------------- group-counter primitives ----------------
__device__ __forceinline__ unsigned ld_acq(const unsigned* p) {
    unsigned v;
    asm volatile("ld.acquire.gpu.u32 %0, [%1];" : "=r"(v) : "l"(p) : "memory");
    return v;
}
__device__ __forceinline__ void red_rel(unsigned* p) {
    asm volatile("red.add.release.gpu.u32 [%0], 1;" :: "l"(p) : "memory");
}

#if HAS_F32X2
__device__ __forceinline__ ull pack2(float lo, float hi) {
    ull d;
    asm("mov.b64 %0, {%1, %2};" : "=l"(d) : "f"(lo), "f"(hi));
    return d;
}
__device__ __forceinline__ ull ffma2(ull a, ull b, ull c) {
    ull d;
    asm("fma.rn.f32x2 %0, %1, %2, %3;" : "=l"(d) : "l"(a), "l"(b), "l"(c));
    return d;
}
#endif

// =============================================================================
// Phase 1: xv[m][n] = X[m][:] @ V[:][n] + b[n] + b2[n]  (unchanged — proven)
// =============================================================================
__global__ __launch_bounds__(256)
void xv_gemm(const float* __restrict__ X, const float* __restrict__ V,
             const float* __restrict__ b1, const float* __restrict__ b2) {
    __shared__ float As[16][132];
    __shared__ float Bs[16][132];

    const int tid = threadIdx.x;
    const int m0  = blockIdx.y * 128;
    const int n0  = blockIdx.x * 128;
    const int ty  = tid >> 4;
    const int tx  = tid & 15;

    float acc[8][8];
    #pragma unroll
    for (int i = 0; i < 8; i++)
        #pragma unroll
        for (int j = 0; j < 8; j++) acc[i][j] = 0.f;

    for (int k0 = 0; k0 < IN_SZ; k0 += 16) {
        #pragma unroll
        for (int i = 0; i < 2; i++) {
            int lin = i * 256 + tid;
            int row = lin >> 2, q = lin & 3;
            float4 v = *(const float4*)(X + (size_t)(m0 + row) * IN_SZ + k0 + q * 4);
            As[q * 4 + 0][row] = v.x;
            As[q * 4 + 1][row] = v.y;
            As[q * 4 + 2][row] = v.z;
            As[q * 4 + 3][row] = v.w;
        }
        #pragma unroll
        for (int i = 0; i < 2; i++) {
            int lin  = i * 256 + tid;
            int krow = lin >> 5, c4 = lin & 31;
            *(float4*)&Bs[krow][c4 * 4] =
                *(const float4*)(V + (size_t)(k0 + krow) * HID + n0 + c4 * 4);
        }
        __syncthreads();
        #pragma unroll
        for (int k = 0; k < 16; k++) {
            float a[8], bb[8];
            *(float4*)&a[0]  = *(float4*)&As[k][ty * 8];
            *(float4*)&a[4]  = *(float4*)&As[k][ty * 8 + 4];
            *(float4*)&bb[0] = *(float4*)&Bs[k][tx * 8];
            *(float4*)&bb[4] = *(float4*)&Bs[k][tx * 8 + 4];
            #pragma unroll
            for (int i = 0; i < 8; i++)
                #pragma unroll
                for (int j = 0; j < 8; j++)
                    acc[i][j] = fmaf(a[i], bb[j], acc[i][j]);
        }
        __syncthreads();
    }

    float bsum[8];
    #pragma unroll
    for (int j = 0; j < 8; j++)
        bsum[j] = b1[n0 + tx * 8 + j] + b2[n0 + tx * 8 + j];

    #pragma unroll
    for (int i = 0; i < 8; i++) {
        float* dst = g_xv + (size_t)(m0 + ty * 8 + i) * HID + n0 + tx * 8;
        float4 v0 = make_float4(acc[i][0] + bsum[0], acc[i][1] + bsum[1],
                                acc[i][2] + bsum[2], acc[i][3] + bsum[3]);
        float4 v1 = make_float4(acc[i][4] + bsum[4], acc[i][5] + bsum[5],
                                acc[i][6] + bsum[6], acc[i][7] + bsum[7]);
        *(float4*)dst       = v0;
        *(float4*)(dst + 4) = v1;
    }
}

// =============================================================================
// Phase 2: persistent recurrence — R13 mainloop + producer-group dataflow sync.
//   No per-step global barrier. h_t and h_{t+1} live at different addresses
//   (no WAR); RAW is enforced per k-block: j-block j's h columns are produced
//   exactly by CTAs 16j..16j+15 (group j). Producers release a per-group
//   monotone counter after their epilogue stores; consumers poll the 8
//   counters in parallel at step top and re-poll lagging groups just before
//   their j-block, overlapping stragglers with compute of ready groups.
// =============================================================================
__global__ __launch_bounds__(TPB2, 1)
void rnn_persistent(const float* __restrict__ W, float* out) {
    extern __shared__ float sm[];
    float* Wp = sm;                  // 4096 float2 (32KB): paired W, interleaved
    float* Ps = sm + 8 * 1024;       // partials: [32 ks][512 outputs + 4 pad]
    const int PSTR = 516;

    const int tid   = threadIdx.x;
    const int lane  = tid & 31;
    const int cbase = blockIdx.x * CPC;
    const int ks    = tid & 31;      // lane = k-split index
    const int wtile = tid >> 5;      // warp id 0..15 -> batch rows wtile*4..+3
    const unsigned FULLM = 0xFFFFFFFFu;

    // Pack W slice into paired-interleaved layout (see R13)
    for (int i = tid; i < 4 * 1024; i += TPB2) {
        int p = i >> 10, k = i & 1023;
        float w0 = W[(size_t)k * HID + cbase + 2 * p];
        float w1 = W[(size_t)k * HID + cbase + 2 * p + 1];
        int j = k >> 7, ksk = (k >> 2) & 31, kq = k & 3;
        int idx = ((j * 8 + p * 2 + (kq >> 1)) * 32 + ksk) * 2 + (kq & 1);
        ((float2*)Wp)[idx] = make_float2(w0, w1);
    }

    // ---- startup: snapshot phase, 2 full barriers around group-base reads ----
    __shared__ unsigned s_base;
    if (tid == 0) {
        unsigned p;
        asm volatile("ld.acquire.gpu.u32 %0, [%1];" : "=r"(p) : "l"(&g_phase) : "memory");
        s_base = p;
    }
    __syncthreads();
    const unsigned base = s_base;

    if (tid == 0) { grid_arrive(); grid_wait(base + 1u); }   // barrier #1
    __syncthreads();
    // every warp: lanes 0-7 snapshot their group's counter base
    unsigned gbase_l = (lane < 8) ? ld_acq(&g_gc[lane * 32]) : 0u;
    __syncthreads();
    if (tid == 0) { grid_arrive(); grid_wait(base + 2u); }   // barrier #2
    __syncthreads();
    // no group arrival can precede any base read past this point

    // Each thread finalizes ONE output o = tid  (o = b*8 + c)
    const int ob = tid >> 3;
    const size_t xv_off = (size_t)ob * HID + cbase + (tid & 7);
    float xv = g_xv[xv_off];

    const size_t hrow0 = (size_t)wtile * 4 * HID + (size_t)ks * 4;
    const int myg = blockIdx.x >> 4;            // producer group of this CTA

    for (int t = 0; t < S_LEN; t++) {
#if HAS_F32X2
        ull acc2[4][4];
        #pragma unroll
        for (int b = 0; b < 4; b++)
            #pragma unroll
            for (int p = 0; p < 4; p++) acc2[b][p] = 0ULL;
#else
        float acc[4][8];
        #pragma unroll
        for (int b = 0; b < 4; b++)
            #pragma unroll
            for (int c = 0; c < 8; c++) acc[b][c] = 0.f;
#endif

        if (t > 0) {
            // ---- group readiness: parallel 8-lane poll (threshold 16*t) ----
            const unsigned thr_l = gbase_l + 16u * (unsigned)t;
            unsigned rdy;
            {
                bool ok = true;
                if (lane < 8)
                    ok = ((int)(ld_acq(&g_gc[lane * 32]) - thr_l) >= 0);
                rdy = __ballot_sync(FULLM, ok);
            }
            // group 0 must be ready before the h prologue
            if (!(rdy & 1u)) {
                unsigned thr0 = __shfl_sync(FULLM, thr_l, 0);
                if (lane == 0)
                    while ((int)(ld_acq(&g_gc[0]) - thr0) < 0) {}
                __syncwarp();
            }

            const float* prev = out + (size_t)(t - 1) * BH + hrow0;

            float4 h4[4];
            #pragma unroll
            for (int b = 0; b < 4; b++)
                h4[b] = __ldcg((const float4*)(prev + (size_t)b * HID));

            #pragma unroll 1
            for (int j = 0; j < 8; j++) {
                float4 hn[4];
                if (j < 7) {
                    // ensure group j+1 produced its h columns before prefetch
                    if (!((rdy >> (j + 1)) & 1u)) {
                        unsigned thrg = __shfl_sync(FULLM, thr_l, j + 1);
                        if (lane == 0)
                            while ((int)(ld_acq(&g_gc[(j + 1) * 32]) - thrg) < 0) {}
                        __syncwarp();
                    }
                    #pragma unroll
                    for (int b = 0; b < 4; b++)
                        hn[b] = __ldcg((const float4*)(prev + (size_t)b * HID + j * 128 + 128));
                }

#if HAS_F32X2
                ulonglong2 wv[8];
                const ulonglong2* wj = (const ulonglong2*)Wp + (size_t)(j * 8) * 32 + ks;
                #pragma unroll
                for (int i = 0; i < 8; i++)
                    wv[i] = wj[(size_t)i * 32];

                #pragma unroll
                for (int kk = 0; kk < 4; kk++) {
                    const int ih = kk >> 1;
                    ull w0 = (kk & 1) ? wv[0 + ih].y : wv[0 + ih].x;
                    ull w1 = (kk & 1) ? wv[2 + ih].y : wv[2 + ih].x;
                    ull w2 = (kk & 1) ? wv[4 + ih].y : wv[4 + ih].x;
                    ull w3 = (kk & 1) ? wv[6 + ih].y : wv[6 + ih].x;
                    #pragma unroll
                    for (int b = 0; b < 4; b++) {
                        float hk = ((const float*)&h4[b])[kk];
                        ull hd = pack2(hk, hk);
                        acc2[b][0] = ffma2(hd, w0, acc2[b][0]);
                        acc2[b][1] = ffma2(hd, w1, acc2[b][1]);
                        acc2[b][2] = ffma2(hd, w2, acc2[b][2]);
                        acc2[b][3] = ffma2(hd, w3, acc2[b][3]);
                    }
                }
#else
                float4 wq[8];
                const float4* wj = (const float4*)Wp + (size_t)(j * 8) * 32 + ks;
                #pragma unroll
                for (int i = 0; i < 8; i++)
                    wq[i] = wj[(size_t)i * 32];

                #pragma unroll
                for (int kk = 0; kk < 4; kk++) {
                    const int ih = kk >> 1;
                    #pragma unroll
                    for (int b = 0; b < 4; b++) {
                        float hk = ((const float*)&h4[b])[kk];
                        #pragma unroll
                        for (int p = 0; p < 4; p++) {
                            const float4& v = wq[p * 2 + ih];
                            float wx = (kk & 1) ? v.z : v.x;
                            float wy = (kk & 1) ? v.w : v.y;
                            acc[b][2 * p]     = fmaf(hk, wx, acc[b][2 * p]);
                            acc[b][2 * p + 1] = fmaf(hk, wy, acc[b][2 * p + 1]);
                        }
                    }
                }
#endif
                if (j < 7) {
                    #pragma unroll
                    for (int b = 0; b < 4; b++) h4[b] = hn[b];
                }
            }
        }

        // ---- k-split partial store (layout identical to R13) ----
        float* prow = Ps + ks * PSTR + wtile * 32;
#if HAS_F32X2
        #pragma unroll
        for (int b = 0; b < 4; b++) {
            *(ulonglong2*)(prow + b * 8)     = make_ulonglong2(acc2[b][0], acc2[b][1]);
            *(ulonglong2*)(prow + b * 8 + 4) = make_ulonglong2(acc2[b][2], acc2[b][3]);
        }
#else
        #pragma unroll
        for (int b = 0; b < 4; b++) {
            *(float4*)(prow + b * 8)     = make_float4(acc[b][0], acc[b][1],
                                                       acc[b][2], acc[b][3]);
            *(float4*)(prow + b * 8 + 4) = make_float4(acc[b][4], acc[b][5],
                                                       acc[b][6], acc[b][7]);
        }
#endif
        __syncthreads();

        // ---- reduction: 32 conflict-free LDS.32 (R13, proven) ----
        float s = 0.f;
        #pragma unroll
        for (int p = 0; p < 32; p++)
            s += Ps[p * PSTR + tid];
        float r = tanhf(s + xv);

        out[(size_t)t * BH + xv_off] = r;
        if (t == S_LEN - 1)
            out[(size_t)S_LEN * BH + xv_off] = r;

        __syncthreads();                 // all out-stores + Ps reads complete
        if (tid == 0) red_rel(&g_gc[myg * 32]);   // publish h_t (release)

        if (t + 1 < S_LEN)
            xv = g_xv[(size_t)(t + 1) * BH + xv_off];
    }
}

// =============================================================================
// launch
// =============================================================================
extern "C" void kernel_launch(void* const* d_in, const int* in_sizes, int n_in,
                              void* d_out, int out_size) {
    const float* x  = (const float*)d_in[0];
    const float* V  = (const float*)d_in[1];
    const float* W  = (const float*)d_in[2];
    const float* b  = (const float*)d_in[3];
    const float* b2 = (const float*)d_in[4];
    float* out = (float*)d_out;

    dim3 g1(HID / 128, (S_LEN * BATCH) / 128);
    xv_gemm<<<g1, 256>>>(x, V, b, b2);

    const int smem_bytes = (8 * 1024 + 32 * 516) * (int)sizeof(float); // 98816
    cudaFuncSetAttribute(rnn_persistent,
                         cudaFuncAttributeMaxDynamicSharedMemorySize, smem_bytes);
    rnn_persistent<<<NCTA, TPB2, smem_bytes>>>(W, out);
}

// round 16
// speedup vs baseline: 1.2148x; 1.2148x over previous
#include <cuda_runtime.h>
#include <math.h>
#include <stdint.h>

#define S_LEN 512
#define BATCH 64
#define IN_SZ 256
#define HID   1024
#define NCTA  128
#define CPC   8            // columns per CTA = HID/NCTA
#define TPB2  512          // recurrence threads: 16 warps
#define BH    (BATCH * HID)

typedef unsigned long long ull;

// packed f32x2 FMA exists only in the arch-specific ('a') compilation pass
#if (defined(__CUDA_ARCH_FEAT_SM103_ALL) || \
     (defined(__CUDA_ARCH_SPECIFIC__) && (__CUDA_ARCH_SPECIFIC__ == 1030)))
#define HAS_F32X2 1
#else
#define HAS_F32X2 0
#endif

// ---------------- scratch / sync state (no allocs allowed) ----------------
__device__ float    g_xv[(size_t)S_LEN * BATCH * HID];   // x@V + b + b2
__device__ unsigned g_grp[8 * 32];   // tree barrier: 8 group counters (128B apart)
__device__ unsigned g_root = 0;      // tree barrier: root counter
__device__ unsigned g_phase = 0;     // barrier generation (monotone, replay-safe)

// ---------------- two-level tree grid barrier (128 CTAs = 8 x 16) -----------
// Arrival: group RMW (16 serialized per line, 8 lines parallel) -> root RMW
// (8 serialized) -> phase release. Wait: poll g_phase (single hot line).
// acq_rel RMW chains provide transitive release of all prior stores.
__device__ __forceinline__ void tree_arrive(int myg) {
    unsigned tk;
    asm volatile("atom.add.acq_rel.gpu.u32 %0, [%1], 1;"
                 : "=r"(tk) : "l"(&g_grp[myg * 32]) : "memory");
    if ((tk & 15u) == 15u) {
        unsigned tr;
        asm volatile("atom.add.acq_rel.gpu.u32 %0, [%1], 1;"
                     : "=r"(tr) : "l"(&g_root) : "memory");
        if ((tr & 7u) == 7u)
            asm volatile("red.add.release.gpu.u32 [%0], 1;"
                         :: "l"(&g_phase) : "memory");
    }
}
__device__ __forceinline__ void phase_wait(unsigned target) {
    unsigned p;
    do {
        asm volatile("ld.acquire.gpu.u32 %0, [%1];"
                     : "=r"(p) : "l"(&g_phase) : "memory");
    } while ((int)(p - target) < 0);
}

#if HAS_F32X2
__device__ __forceinline__ ull pack2(float lo, float hi) {
    ull d;
    asm("mov.b64 %0, {%1, %2};" : "=l"(d) : "f"(lo), "f"(hi));
    return d;
}
__device__ __forceinline__ ull ffma2(ull a, ull b, ull c) {
    ull d;
    asm("fma.rn.f32x2 %0, %1, %2, %3;" : "=l"(d) : "l"(a), "l"(b), "l"(c));
    return d;
}
#endif

// =============================================================================
// Phase 1: xv[m][n] = X[m][:] @ V[:][n] + b[n] + b2[n]  (unchanged — proven)
// =============================================================================
__global__ __launch_bounds__(256)
void xv_gemm(const float* __restrict__ X, const float* __restrict__ V,
             const float* __restrict__ b1, const float* __restrict__ b2) {
    __shared__ float As[16][132];
    __shared__ float Bs[16][132];

    const int tid = threadIdx.x;
    const int m0  = blockIdx.y * 128;
    const int n0  = blockIdx.x * 128;
    const int ty  = tid >> 4;
    const int tx  = tid & 15;

    float acc[8][8];
    #pragma unroll
    for (int i = 0; i < 8; i++)
        #pragma unroll
        for (int j = 0; j < 8; j++) acc[i][j] = 0.f;

    for (int k0 = 0; k0 < IN_SZ; k0 += 16) {
        #pragma unroll
        for (int i = 0; i < 2; i++) {
            int lin = i * 256 + tid;
            int row = lin >> 2, q = lin & 3;
            float4 v = *(const float4*)(X + (size_t)(m0 + row) * IN_SZ + k0 + q * 4);
            As[q * 4 + 0][row] = v.x;
            As[q * 4 + 1][row] = v.y;
            As[q * 4 + 2][row] = v.z;
            As[q * 4 + 3][row] = v.w;
        }
        #pragma unroll
        for (int i = 0; i < 2; i++) {
            int lin  = i * 256 + tid;
            int krow = lin >> 5, c4 = lin & 31;
            *(float4*)&Bs[krow][c4 * 4] =
                *(const float4*)(V + (size_t)(k0 + krow) * HID + n0 + c4 * 4);
        }
        __syncthreads();
        #pragma unroll
        for (int k = 0; k < 16; k++) {
            float a[8], bb[8];
            *(float4*)&a[0]  = *(float4*)&As[k][ty * 8];
            *(float4*)&a[4]  = *(float4*)&As[k][ty * 8 + 4];
            *(float4*)&bb[0] = *(float4*)&Bs[k][tx * 8];
            *(float4*)&bb[4] = *(float4*)&Bs[k][tx * 8 + 4];
            #pragma unroll
            for (int i = 0; i < 8; i++)
                #pragma unroll
                for (int j = 0; j < 8; j++)
                    acc[i][j] = fmaf(a[i], bb[j], acc[i][j]);
        }
        __syncthreads();
    }

    float bsum[8];
    #pragma unroll
    for (int j = 0; j < 8; j++)
        bsum[j] = b1[n0 + tx * 8 + j] + b2[n0 + tx * 8 + j];

    #pragma unroll
    for (int i = 0; i < 8; i++) {
        float* dst = g_xv + (size_t)(m0 + ty * 8 + i) * HID + n0 + tx * 8;
        float4 v0 = make_float4(acc[i][0] + bsum[0], acc[i][1] + bsum[1],
                                acc[i][2] + bsum[2], acc[i][3] + bsum[3]);
        float4 v1 = make_float4(acc[i][4] + bsum[4], acc[i][5] + bsum[5],
                                acc[i][6] + bsum[6], acc[i][7] + bsum[7]);
        *(float4*)dst       = v0;
        *(float4*)(dst + 4) = v1;
    }
}

// =============================================================================
// Phase 2: persistent recurrence — R13 mainloop + tree barrier.
//   128 CTAs x 512 threads (occ 25%). W pre-paired in smem for FFMA2 (zero
//   runtime w-packing); per j: 8 LDS.128 (W pairs) + 4 LDG.128.cg (h,
//   prefetched one block ahead) + 64 FFMA2. Reduction: 32 conflict-free
//   LDS.32 with 4-way ILP sum. Step barrier: two-level tree arrival.
// =============================================================================
__global__ __launch_bounds__(TPB2, 1)
void rnn_persistent(const float* __restrict__ W, float* out) {
    extern __shared__ float sm[];
    float* Wp = sm;                  // 4096 float2 (32KB): paired W, interleaved
    float* Ps = sm + 8 * 1024;       // partials: [32 ks][512 outputs + 4 pad]
    const int PSTR = 516;

    const int tid   = threadIdx.x;
    const int cbase = blockIdx.x * CPC;
    const int ks    = tid & 31;      // lane = k-split index
    const int wtile = tid >> 5;      // warp id 0..15 -> batch rows wtile*4..+3
    const int myg   = blockIdx.x >> 4;   // barrier group

    // Pack W slice into paired-interleaved layout (see R13)
    for (int i = tid; i < 4 * 1024; i += TPB2) {
        int p = i >> 10, k = i & 1023;
        float w0 = W[(size_t)k * HID + cbase + 2 * p];
        float w1 = W[(size_t)k * HID + cbase + 2 * p + 1];
        int j = k >> 7, ksk = (k >> 2) & 31, kq = k & 3;
        int idx = ((j * 8 + p * 2 + (kq >> 1)) * 32 + ksk) * 2 + (kq & 1);
        ((float2*)Wp)[idx] = make_float2(w0, w1);
    }

    __shared__ unsigned s_base;
    if (tid == 0) {
        unsigned p;
        asm volatile("ld.acquire.gpu.u32 %0, [%1];" : "=r"(p) : "l"(&g_phase) : "memory");
        s_base = p;
    }
    __syncthreads();
    const unsigned base = s_base;

    // Each thread finalizes ONE output o = tid  (o = b*8 + c)
    const int ob = tid >> 3;
    const size_t xv_off = (size_t)ob * HID + cbase + (tid & 7);
    float xv = g_xv[xv_off];

    const size_t hrow0 = (size_t)wtile * 4 * HID + (size_t)ks * 4;

    for (int t = 0; t < S_LEN; t++) {
#if HAS_F32X2
        ull acc2[4][4];
        #pragma unroll
        for (int b = 0; b < 4; b++)
            #pragma unroll
            for (int p = 0; p < 4; p++) acc2[b][p] = 0ULL;

        if (t > 0) {
            const float* prev = out + (size_t)(t - 1) * BH + hrow0;

            float4 h4[4];
            #pragma unroll
            for (int b = 0; b < 4; b++)
                h4[b] = __ldcg((const float4*)(prev + (size_t)b * HID));

            #pragma unroll 1
            for (int j = 0; j < 8; j++) {
                float4 hn[4];
                if (j < 7) {
                    #pragma unroll
                    for (int b = 0; b < 4; b++)
                        hn[b] = __ldcg((const float4*)(prev + (size_t)b * HID + j * 128 + 128));
                }

                ulonglong2 wv[8];
                const ulonglong2* wj = (const ulonglong2*)Wp + (size_t)(j * 8) * 32 + ks;
                #pragma unroll
                for (int i = 0; i < 8; i++)
                    wv[i] = wj[(size_t)i * 32];

                #pragma unroll
                for (int kk = 0; kk < 4; kk++) {
                    const int ih = kk >> 1;
                    ull w0 = (kk & 1) ? wv[0 + ih].y : wv[0 + ih].x;
                    ull w1 = (kk & 1) ? wv[2 + ih].y : wv[2 + ih].x;
                    ull w2 = (kk & 1) ? wv[4 + ih].y : wv[4 + ih].x;
                    ull w3 = (kk & 1) ? wv[6 + ih].y : wv[6 + ih].x;
                    #pragma unroll
                    for (int b = 0; b < 4; b++) {
                        float hk = ((const float*)&h4[b])[kk];
                        ull hd = pack2(hk, hk);
                        acc2[b][0] = ffma2(hd, w0, acc2[b][0]);
                        acc2[b][1] = ffma2(hd, w1, acc2[b][1]);
                        acc2[b][2] = ffma2(hd, w2, acc2[b][2]);
                        acc2[b][3] = ffma2(hd, w3, acc2[b][3]);
                    }
                }

                if (j < 7) {
                    #pragma unroll
                    for (int b = 0; b < 4; b++) h4[b] = hn[b];
                }
            }
        }

        float* prow = Ps + ks * PSTR + wtile * 32;
        #pragma unroll
        for (int b = 0; b < 4; b++) {
            *(ulonglong2*)(prow + b * 8)     = make_ulonglong2(acc2[b][0], acc2[b][1]);
            *(ulonglong2*)(prow + b * 8 + 4) = make_ulonglong2(acc2[b][2], acc2[b][3]);
        }
#else
        float acc[4][8];
        #pragma unroll
        for (int b = 0; b < 4; b++)
            #pragma unroll
            for (int c = 0; c < 8; c++) acc[b][c] = 0.f;

        if (t > 0) {
            const float* prev = out + (size_t)(t - 1) * BH + hrow0;
            float4 h4[4];
            #pragma unroll
            for (int b = 0; b < 4; b++)
                h4[b] = __ldcg((const float4*)(prev + (size_t)b * HID));

            #pragma unroll 1
            for (int j = 0; j < 8; j++) {
                float4 hn[4];
                if (j < 7) {
                    #pragma unroll
                    for (int b = 0; b < 4; b++)
                        hn[b] = __ldcg((const float4*)(prev + (size_t)b * HID + j * 128 + 128));
                }
                float4 wq[8];
                const float4* wj = (const float4*)Wp + (size_t)(j * 8) * 32 + ks;
                #pragma unroll
                for (int i = 0; i < 8; i++)
                    wq[i] = wj[(size_t)i * 32];

                #pragma unroll
                for (int kk = 0; kk < 4; kk++) {
                    const int ih = kk >> 1;
                    #pragma unroll
                    for (int b = 0; b < 4; b++) {
                        float hk = ((const float*)&h4[b])[kk];
                        #pragma unroll
                        for (int p = 0; p < 4; p++) {
                            const float4& v = wq[p * 2 + ih];
                            float wx = (kk & 1) ? v.z : v.x;
                            float wy = (kk & 1) ? v.w : v.y;
                            acc[b][2 * p]     = fmaf(hk, wx, acc[b][2 * p]);
                            acc[b][2 * p + 1] = fmaf(hk, wy, acc[b][2 * p + 1]);
                        }
                    }
                }
                if (j < 7) {
                    #pragma unroll
                    for (int b = 0; b < 4; b++) h4[b] = hn[b];
                }
            }
        }
        float* prow = Ps + ks * PSTR + wtile * 32;
        #pragma unroll
        for (int b = 0; b < 4; b++) {
            *(float4*)(prow + b * 8)     = make_float4(acc[b][0], acc[b][1],
                                                       acc[b][2], acc[b][3]);
            *(float4*)(prow + b * 8 + 4) = make_float4(acc[b][4], acc[b][5],
                                                       acc[b][6], acc[b][7]);
        }
#endif
        __syncthreads();

        // ---- reduction: 32 conflict-free LDS.32, 4-way ILP sum ----
        float s0 = 0.f, s1 = 0.f, s2 = 0.f, s3 = 0.f;
        #pragma unroll
        for (int p = 0; p < 8; p++) {
            s0 += Ps[(4 * p + 0) * PSTR + tid];
            s1 += Ps[(4 * p + 1) * PSTR + tid];
            s2 += Ps[(4 * p + 2) * PSTR + tid];
            s3 += Ps[(4 * p + 3) * PSTR + tid];
        }
        float r = tanhf(((s0 + s1) + (s2 + s3)) + xv);

        out[(size_t)t * BH + xv_off] = r;
        if (t == S_LEN - 1)
            out[(size_t)S_LEN * BH + xv_off] = r;

        // ---- split tree barrier: arrive, prefetch next xv, wait ----
        __syncthreads();                  // stores issued + Ps reads done
        if (tid == 0) tree_arrive(myg);
        if (t + 1 < S_LEN)
            xv = g_xv[(size_t)(t + 1) * BH + xv_off];
        if (tid == 0) phase_wait(base + (unsigned)t + 1u);
        __syncthreads();
    }
}

// =============================================================================
// launch
// =============================================================================
extern "C" void kernel_launch(void* const* d_in, const int* in_sizes, int n_in,
                              void* d_out, int out_size) {
    const float* x  = (const float*)d_in[0];
    const float* V  = (const float*)d_in[1];
    const float* W  = (const float*)d_in[2];
    const float* b  = (const float*)d_in[3];
    const float* b2 = (const float*)d_in[4];
    float* out = (float*)d_out;

    dim3 g1(HID / 128, (S_LEN * BATCH) / 128);
    xv_gemm<<<g1, 256>>>(x, V, b, b2);

    const int smem_bytes = (8 * 1024 + 32 * 516) * (int)sizeof(float); // 98816
    cudaFuncSetAttribute(rnn_persistent,
                         cudaFuncAttributeMaxDynamicSharedMemorySize, smem_bytes);
    rnn_persistent<<<NCTA, TPB2, smem_bytes>>>(W, out);
}

// round 17
// speedup vs baseline: 1.4229x; 1.1713x over previous
#include <cuda_runtime.h>
#include <math.h>
#include <stdint.h>

#define S_LEN 512
#define BATCH 64
#define IN_SZ 256
#define HID   1024
#define NCTA  128
#define CPC   8            // columns per CTA = HID/NCTA
#define TPB2  512          // recurrence threads: 16 warps
#define BH    (BATCH * HID)

typedef unsigned long long ull;

// packed f32x2 FMA exists only in the arch-specific ('a') compilation pass
#if (defined(__CUDA_ARCH_FEAT_SM103_ALL) || \
     (defined(__CUDA_ARCH_SPECIFIC__) && (__CUDA_ARCH_SPECIFIC__ == 1030)))
#define HAS_F32X2 1
#else
#define HAS_F32X2 0
#endif

// ---------------- scratch / sync state (no allocs allowed) ----------------
__device__ float    g_xv[(size_t)S_LEN * BATCH * HID];   // x@V + b + b2
__device__ unsigned g_count = 0;   // startup barrier arrivals (monotone)
__device__ unsigned g_phase = 0;   // startup barrier generation (monotone)
__device__ unsigned g_step  = 0;   // per-step arrival counter (monotone)

// ---------------- startup-only full grid barrier (proven scheme) ------------
__device__ __forceinline__ void grid_arrive() {
    unsigned ticket;
    asm volatile("atom.add.acq_rel.gpu.u32 %0, [%1], 1;"
                 : "=r"(ticket) : "l"(&g_count) : "memory");
    if ((ticket & (NCTA - 1)) == (NCTA - 1)) {
        asm volatile("red.add.release.gpu.u32 [%0], 1;"
                     :: "l"(&g_phase) : "memory");
    }
}
__device__ __forceinline__ void grid_wait(unsigned target) {
    unsigned p;
    do {
        asm volatile("ld.acquire.gpu.u32 %0, [%1];"
                     : "=r"(p) : "l"(&g_phase) : "memory");
    } while ((int)(p - target) < 0);
}

// ---------------- step barrier: count-polling (no release hop) --------------
__device__ __forceinline__ void step_arrive() {
    unsigned t;
    asm volatile("atom.add.acq_rel.gpu.u32 %0, [%1], 1;"
                 : "=r"(t) : "l"(&g_step) : "memory");
}
__device__ __forceinline__ void step_wait(unsigned target) {
    unsigned v;
    do {
        asm volatile("ld.acquire.gpu.u32 %0, [%1];"
                     : "=r"(v) : "l"(&g_step) : "memory");
    } while ((int)(v - target) < 0);
}

#if HAS_F32X2
__device__ __forceinline__ ull pack2(float lo, float hi) {
    ull d;
    asm("mov.b64 %0, {%1, %2};" : "=l"(d) : "f"(lo), "f"(hi));
    return d;
}
__device__ __forceinline__ ull ffma2(ull a, ull b, ull c) {
    ull d;
    asm("fma.rn.f32x2 %0, %1, %2, %3;" : "=l"(d) : "l"(a), "l"(b), "l"(c));
    return d;
}
#endif

// =============================================================================
// Phase 1: xv[m][n] = X[m][:] @ V[:][n] + b[n] + b2[n]  (unchanged — proven)
// =============================================================================
__global__ __launch_bounds__(256)
void xv_gemm(const float* __restrict__ X, const float* __restrict__ V,
             const float* __restrict__ b1, const float* __restrict__ b2) {
    __shared__ float As[16][132];
    __shared__ float Bs[16][132];

    const int tid = threadIdx.x;
    const int m0  = blockIdx.y * 128;
    const int n0  = blockIdx.x * 128;
    const int ty  = tid >> 4;
    const int tx  = tid & 15;

    float acc[8][8];
    #pragma unroll
    for (int i = 0; i < 8; i++)
        #pragma unroll
        for (int j = 0; j < 8; j++) acc[i][j] = 0.f;

    for (int k0 = 0; k0 < IN_SZ; k0 += 16) {
        #pragma unroll
        for (int i = 0; i < 2; i++) {
            int lin = i * 256 + tid;
            int row = lin >> 2, q = lin & 3;
            float4 v = *(const float4*)(X + (size_t)(m0 + row) * IN_SZ + k0 + q * 4);
            As[q * 4 + 0][row] = v.x;
            As[q * 4 + 1][row] = v.y;
            As[q * 4 + 2][row] = v.z;
            As[q * 4 + 3][row] = v.w;
        }
        #pragma unroll
        for (int i = 0; i < 2; i++) {
            int lin  = i * 256 + tid;
            int krow = lin >> 5, c4 = lin & 31;
            *(float4*)&Bs[krow][c4 * 4] =
                *(const float4*)(V + (size_t)(k0 + krow) * HID + n0 + c4 * 4);
        }
        __syncthreads();
        #pragma unroll
        for (int k = 0; k < 16; k++) {
            float a[8], bb[8];
            *(float4*)&a[0]  = *(float4*)&As[k][ty * 8];
            *(float4*)&a[4]  = *(float4*)&As[k][ty * 8 + 4];
            *(float4*)&bb[0] = *(float4*)&Bs[k][tx * 8];
            *(float4*)&bb[4] = *(float4*)&Bs[k][tx * 8 + 4];
            #pragma unroll
            for (int i = 0; i < 8; i++)
                #pragma unroll
                for (int j = 0; j < 8; j++)
                    acc[i][j] = fmaf(a[i], bb[j], acc[i][j]);
        }
        __syncthreads();
    }

    float bsum[8];
    #pragma unroll
    for (int j = 0; j < 8; j++)
        bsum[j] = b1[n0 + tx * 8 + j] + b2[n0 + tx * 8 + j];

    #pragma unroll
    for (int i = 0; i < 8; i++) {
        float* dst = g_xv + (size_t)(m0 + ty * 8 + i) * HID + n0 + tx * 8;
        float4 v0 = make_float4(acc[i][0] + bsum[0], acc[i][1] + bsum[1],
                                acc[i][2] + bsum[2], acc[i][3] + bsum[3]);
        float4 v1 = make_float4(acc[i][4] + bsum[4], acc[i][5] + bsum[5],
                                acc[i][6] + bsum[6], acc[i][7] + bsum[7]);
        *(float4*)dst       = v0;
        *(float4*)(dst + 4) = v1;
    }
}

// =============================================================================
// Phase 2: persistent recurrence — R13 mainloop + count-polling step barrier.
//   128 CTAs x 512 threads (occ 25%). W pre-paired in smem for FFMA2 (zero
//   runtime w-packing); per j: 8 LDS.128 (W pairs) + 4 LDG.128.cg (h,
//   prefetched one block ahead) + 64 FFMA2. Reduction: 32 conflict-free
//   LDS.32, 4-way ILP sum. Step barrier: arrivals on g_step; waiters poll
//   g_step directly (completion visible the instant the 128th RMW lands —
//   no release hop, no second L2 round-trip).
// =============================================================================
__global__ __launch_bounds__(TPB2, 1)
void rnn_persistent(const float* __restrict__ W, float* out) {
    extern __shared__ float sm[];
    float* Wp = sm;                  // 4096 float2 (32KB): paired W, interleaved
    float* Ps = sm + 8 * 1024;       // partials: [32 ks][512 outputs + 4 pad]
    const int PSTR = 516;

    const int tid   = threadIdx.x;
    const int cbase = blockIdx.x * CPC;
    const int ks    = tid & 31;      // lane = k-split index
    const int wtile = tid >> 5;      // warp id 0..15 -> batch rows wtile*4..+3

    // Pack W slice into paired-interleaved layout (see R13)
    for (int i = tid; i < 4 * 1024; i += TPB2) {
        int p = i >> 10, k = i & 1023;
        float w0 = W[(size_t)k * HID + cbase + 2 * p];
        float w1 = W[(size_t)k * HID + cbase + 2 * p + 1];
        int j = k >> 7, ksk = (k >> 2) & 31, kq = k & 3;
        int idx = ((j * 8 + p * 2 + (kq >> 1)) * 32 + ksk) * 2 + (kq & 1);
        ((float2*)Wp)[idx] = make_float2(w0, w1);
    }

    // ---- startup: snapshot g_step base between two proven full barriers ----
    __shared__ unsigned s_base, s_sc;
    if (tid == 0) {
        unsigned p;
        asm volatile("ld.acquire.gpu.u32 %0, [%1];" : "=r"(p) : "l"(&g_phase) : "memory");
        s_base = p;
    }
    __syncthreads();
    const unsigned base = s_base;

    if (tid == 0) { grid_arrive(); grid_wait(base + 1u); }   // barrier #1
    __syncthreads();
    if (tid == 0) {
        unsigned v;
        asm volatile("ld.acquire.gpu.u32 %0, [%1];" : "=r"(v) : "l"(&g_step) : "memory");
        s_sc = v;
    }
    __syncthreads();
    if (tid == 0) { grid_arrive(); grid_wait(base + 2u); }   // barrier #2
    __syncthreads();
    const unsigned scbase = s_sc;   // no step arrival can precede this snapshot

    // Each thread finalizes ONE output o = tid  (o = b*8 + c)
    const int ob = tid >> 3;
    const size_t xv_off = (size_t)ob * HID + cbase + (tid & 7);
    float xv = g_xv[xv_off];

    const size_t hrow0 = (size_t)wtile * 4 * HID + (size_t)ks * 4;

    for (int t = 0; t < S_LEN; t++) {
#if HAS_F32X2
        ull acc2[4][4];
        #pragma unroll
        for (int b = 0; b < 4; b++)
            #pragma unroll
            for (int p = 0; p < 4; p++) acc2[b][p] = 0ULL;

        if (t > 0) {
            const float* prev = out + (size_t)(t - 1) * BH + hrow0;

            float4 h4[4];
            #pragma unroll
            for (int b = 0; b < 4; b++)
                h4[b] = __ldcg((const float4*)(prev + (size_t)b * HID));

            #pragma unroll 1
            for (int j = 0; j < 8; j++) {
                float4 hn[4];
                if (j < 7) {
                    #pragma unroll
                    for (int b = 0; b < 4; b++)
                        hn[b] = __ldcg((const float4*)(prev + (size_t)b * HID + j * 128 + 128));
                }

                ulonglong2 wv[8];
                const ulonglong2* wj = (const ulonglong2*)Wp + (size_t)(j * 8) * 32 + ks;
                #pragma unroll
                for (int i = 0; i < 8; i++)
                    wv[i] = wj[(size_t)i * 32];

                #pragma unroll
                for (int kk = 0; kk < 4; kk++) {
                    const int ih = kk >> 1;
                    ull w0 = (kk & 1) ? wv[0 + ih].y : wv[0 + ih].x;
                    ull w1 = (kk & 1) ? wv[2 + ih].y : wv[2 + ih].x;
                    ull w2 = (kk & 1) ? wv[4 + ih].y : wv[4 + ih].x;
                    ull w3 = (kk & 1) ? wv[6 + ih].y : wv[6 + ih].x;
                    #pragma unroll
                    for (int b = 0; b < 4; b++) {
                        float hk = ((const float*)&h4[b])[kk];
                        ull hd = pack2(hk, hk);
                        acc2[b][0] = ffma2(hd, w0, acc2[b][0]);
                        acc2[b][1] = ffma2(hd, w1, acc2[b][1]);
                        acc2[b][2] = ffma2(hd, w2, acc2[b][2]);
                        acc2[b][3] = ffma2(hd, w3, acc2[b][3]);
                    }
                }

                if (j < 7) {
                    #pragma unroll
                    for (int b = 0; b < 4; b++) h4[b] = hn[b];
                }
            }
        }

        float* prow = Ps + ks * PSTR + wtile * 32;
        #pragma unroll
        for (int b = 0; b < 4; b++) {
            *(ulonglong2*)(prow + b * 8)     = make_ulonglong2(acc2[b][0], acc2[b][1]);
            *(ulonglong2*)(prow + b * 8 + 4) = make_ulonglong2(acc2[b][2], acc2[b][3]);
        }
#else
        float acc[4][8];
        #pragma unroll
        for (int b = 0; b < 4; b++)
            #pragma unroll
            for (int c = 0; c < 8; c++) acc[b][c] = 0.f;

        if (t > 0) {
            const float* prev = out + (size_t)(t - 1) * BH + hrow0;
            float4 h4[4];
            #pragma unroll
            for (int b = 0; b < 4; b++)
                h4[b] = __ldcg((const float4*)(prev + (size_t)b * HID));

            #pragma unroll 1
            for (int j = 0; j < 8; j++) {
                float4 hn[4];
                if (j < 7) {
                    #pragma unroll
                    for (int b = 0; b < 4; b++)
                        hn[b] = __ldcg((const float4*)(prev + (size_t)b * HID + j * 128 + 128));
                }
                float4 wq[8];
                const float4* wj = (const float4*)Wp + (size_t)(j * 8) * 32 + ks;
                #pragma unroll
                for (int i = 0; i < 8; i++)
                    wq[i] = wj[(size_t)i * 32];

                #pragma unroll
                for (int kk = 0; kk < 4; kk++) {
                    const int ih = kk >> 1;
                    #pragma unroll
                    for (int b = 0; b < 4; b++) {
                        float hk = ((const float*)&h4[b])[kk];
                        #pragma unroll
                        for (int p = 0; p < 4; p++) {
                            const float4& v = wq[p * 2 + ih];
                            float wx = (kk & 1) ? v.z : v.x;
                            float wy = (kk & 1) ? v.w : v.y;
                            acc[b][2 * p]     = fmaf(hk, wx, acc[b][2 * p]);
                            acc[b][2 * p + 1] = fmaf(hk, wy, acc[b][2 * p + 1]);
                        }
                    }
                }
                if (j < 7) {
                    #pragma unroll
                    for (int b = 0; b < 4; b++) h4[b] = hn[b];
                }
            }
        }
        float* prow = Ps + ks * PSTR + wtile * 32;
        #pragma unroll
        for (int b = 0; b < 4; b++) {
            *(float4*)(prow + b * 8)     = make_float4(acc[b][0], acc[b][1],
                                                       acc[b][2], acc[b][3]);
            *(float4*)(prow + b * 8 + 4) = make_float4(acc[b][4], acc[b][5],
                                                       acc[b][6], acc[b][7]);
        }
#endif
        __syncthreads();

        // ---- reduction: 32 conflict-free LDS.32, 4-way ILP sum ----
        float s0 = 0.f, s1 = 0.f, s2 = 0.f, s3 = 0.f;
        #pragma unroll
        for (int p = 0; p < 8; p++) {
            s0 += Ps[(4 * p + 0) * PSTR + tid];
            s1 += Ps[(4 * p + 1) * PSTR + tid];
            s2 += Ps[(4 * p + 2) * PSTR + tid];
            s3 += Ps[(4 * p + 3) * PSTR + tid];
        }
        float r = tanhf(((s0 + s1) + (s2 + s3)) + xv);

        out[(size_t)t * BH + xv_off] = r;
        if (t == S_LEN - 1)
            out[(size_t)S_LEN * BH + xv_off] = r;

        // ---- split step barrier: arrive, prefetch next xv, poll count ----
        __syncthreads();                  // stores issued + Ps reads done
        if (tid == 0) step_arrive();
        if (t + 1 < S_LEN)
            xv = g_xv[(size_t)(t + 1) * BH + xv_off];
        if (tid == 0) step_wait(scbase + (unsigned)(t + 1) * NCTA);
        __syncthreads();
    }
}

// =============================================================================
// launch
// =============================================================================
extern "C" void kernel_launch(void* const* d_in, const int* in_sizes, int n_in,
                              void* d_out, int out_size) {
    const float* x  = (const float*)d_in[0];
    const float* V  = (const float*)d_in[1];
    const float* W  = (const float*)d_in[2];
    const float* b  = (const float*)d_in[3];
    const float* b2 = (const float*)d_in[4];
    float* out = (float*)d_out;

    dim3 g1(HID / 128, (S_LEN * BATCH) / 128);
    xv_gemm<<<g1, 256>>>(x, V, b, b2);

    const int smem_bytes = (8 * 1024 + 32 * 516) * (int)sizeof(float); // 98816
    cudaFuncSetAttribute(rnn_persistent,
                         cudaFuncAttributeMaxDynamicSharedMemorySize, smem_bytes);
    rnn_persistent<<<NCTA, TPB2, smem_bytes>>>(W, out);
}